// round 3
// baseline (speedup 1.0000x reference)
#include <cuda_runtime.h>

// HaarWavelet2D, level=2, x: (8,64,256,256) fp32 -> (low_freq, high_freq) each (8,64,256,256)
//
// Math (verified against jax.image.resize 'linear' semantics):
//   resize in->out linear == half-pixel bilinear with index clamping
//   255->256: out[i] = w*X[i-1] + (1-w)*X[i],  w = (i+0.5)/256, indices clamped [0,254]
//   128->256: even i=2t: 0.25*X[t-1] + 0.75*X[t] ; odd i=2t+1: 0.75*X[t] + 0.25*X[t+1] (clamped)
//
// Pipeline:
//   K1: ll1,hi1 (128x128/ch) directly from x (4x4 neighborhood -> 3x3 ll0 -> low1 quad -> haar)
//   K2: per 32x32 output tile: x tile in smem -> hi0 tile in smem -> outputs

#define NC_MAX 512
#define HW 256
#define IMG (HW*HW)
#define INV256 (1.0f/256.0f)

__device__ float g_ll1[NC_MAX * 128 * 128];
__device__ float g_hi1[NC_MAX * 128 * 128];

__device__ __forceinline__ int clampi(int v, int lo, int hi) {
    return v < lo ? lo : (v > hi ? hi : v);
}

// ---------------- Kernel 1: level-1 haar coeffs from x ----------------
__global__ void __launch_bounds__(256) k_level1(const float* __restrict__ x) {
    int b = blockIdx.x * 32 + threadIdx.x;   // col index in [0,128)
    int a = blockIdx.y * 8 + threadIdx.y;    // row index in [0,128)
    int ch = blockIdx.z;
    const float* xc = x + (size_t)ch * IMG;

    // 4x4 x neighborhood: logical rows 2a-1..2a+2, cols 2b-1..2b+2 (clamped)
    int rows[4], cols[4];
#pragma unroll
    for (int i = 0; i < 4; i++) {
        rows[i] = clampi(2 * a - 1 + i, 0, 255);
        cols[i] = clampi(2 * b - 1 + i, 0, 255);
    }
    float xg[4][4];
#pragma unroll
    for (int i = 0; i < 4; i++) {
        const float* rp = xc + rows[i] * HW;
#pragma unroll
        for (int j = 0; j < 4; j++) xg[i][j] = __ldg(rp + cols[j]);
    }

    // 3x3 ll0 values at logical (k,l) = (2a-1+u, 2b-1+v)
    float LL[3][3];
#pragma unroll
    for (int u = 0; u < 3; u++)
#pragma unroll
        for (int v = 0; v < 3; v++)
            LL[u][v] = 0.25f * (xg[u][v] + xg[u][v + 1] + xg[u + 1][v] + xg[u + 1][v + 1]);

    // low1 at rows r in {2a,2a+1}, cols c in {2b,2b+1}; taps into LL (local coords)
    // r=2a:   taps (max(2a-1,0) -> uy0, 2a -> 1), weight wy0 on first tap
    // r=2a+1: taps (2a -> 1, min(2a+1,254) -> uy2), weight wy1 on first tap
    int uy0 = (a == 0) ? 1 : 0;
    int uy2 = (a == 127) ? 1 : 2;
    int ux0 = (b == 0) ? 1 : 0;
    int ux2 = (b == 127) ? 1 : 2;
    float wy0 = (2 * a + 0.5f) * INV256;  // weight on row tap uy0 (the "i-1" tap)
    float wy1 = (2 * a + 1.5f) * INV256;  // weight on row tap 1 for r=2a+1
    float wx0 = (2 * b + 0.5f) * INV256;
    float wx1 = (2 * b + 1.5f) * INV256;

    // col-interp helper on a given LL row pair
#define COLA(row) (wx0 * LL[row][ux0] + (1.0f - wx0) * LL[row][1])            // c=2b
#define COLB(row) (wx1 * LL[row][1] + (1.0f - wx1) * LL[row][ux2])            // c=2b+1

    float L00 = wy0 * COLA(uy0) + (1.0f - wy0) * COLA(1);   // (2a,   2b)
    float L01 = wy0 * COLB(uy0) + (1.0f - wy0) * COLB(1);   // (2a,   2b+1)
    float L10 = wy1 * COLA(1) + (1.0f - wy1) * COLA(uy2);   // (2a+1, 2b)
    float L11 = wy1 * COLB(1) + (1.0f - wy1) * COLB(uy2);   // (2a+1, 2b+1)
#undef COLA
#undef COLB

    float ll1 = 0.25f * (L00 + L01 + L10 + L11);
    float lh = 0.25f * (L00 + L01 - L10 - L11);
    float hl = 0.25f * (L00 - L01 + L10 - L11);
    float hh = 0.25f * (L00 - L01 - L10 + L11);
    float hi1 = fabsf(lh) + fabsf(hl) + fabsf(hh);

    size_t o = (size_t)ch * (128 * 128) + a * 128 + b;
    g_ll1[o] = ll1;
    g_hi1[o] = hi1;
}

// ---------------- Kernel 2: outputs ----------------
__global__ void __launch_bounds__(256) k_out(const float* __restrict__ x,
                                             float* __restrict__ out, int nc) {
    __shared__ float xs[34][36];
    __shared__ float hs[33][36];

    int ch = blockIdx.z;
    int i0 = blockIdx.y * 32;
    int j0 = blockIdx.x * 32;
    const float* xc = x + (size_t)ch * IMG;
    int tid = threadIdx.y * 32 + threadIdx.x;

    // load x tile with 1-halo: rows i0-1..i0+32, cols j0-1..j0+32 (clamped)
    for (int e = tid; e < 34 * 34; e += 256) {
        int u = e / 34, v = e - u * 34;
        int r = clampi(i0 - 1 + u, 0, 255);
        int c = clampi(j0 - 1 + v, 0, 255);
        xs[u][v] = __ldg(xc + r * HW + c);
    }
    __syncthreads();

    // hi0 tile: k = i0-1+u, l = j0-1+v, u,v in [0,33)
    for (int e = tid; e < 33 * 33; e += 256) {
        int u = e / 33, v = e - u * 33;
        float a = xs[u][v], b = xs[u][v + 1], c = xs[u + 1][v], d = xs[u + 1][v + 1];
        float lh = 0.25f * (a + b - c - d);
        float hl = 0.25f * (a - b + c - d);
        float hh = 0.25f * (a - b - c + d);
        hs[u][v] = fabsf(lh) + fabsf(hl) + fabsf(hh);
    }
    __syncthreads();

    const float* L1 = g_ll1 + (size_t)ch * (128 * 128);
    const float* H1 = g_hi1 + (size_t)ch * (128 * 128);
    size_t nimg = (size_t)nc * IMG;
    float* out_low = out;
    float* out_high = out + nimg;

    int j = j0 + threadIdx.x;
    // hi0 column taps/weight (255->256)
    float wxc = (j + 0.5f) * INV256;
    int va = max(j - 1, 0) - (j0 - 1);
    int vb = min(j, 254) - (j0 - 1);
    // hi1/ll1 column taps (128->256)
    int tj = j >> 1;
    int ca, cb;
    float wca;
    if ((j & 1) == 0) { ca = max(tj - 1, 0); cb = tj; wca = 0.25f; }
    else              { ca = tj; cb = min(tj + 1, 127); wca = 0.75f; }
    float wcb = 1.0f - wca;

#pragma unroll
    for (int k = 0; k < 4; k++) {
        int i = i0 + threadIdx.y + k * 8;
        // hi0 bilinear (smem)
        float wyc = (i + 0.5f) * INV256;
        int ua = max(i - 1, 0) - (i0 - 1);
        int ub = min(i, 254) - (i0 - 1);
        float h0 = wyc * (wxc * hs[ua][va] + (1.0f - wxc) * hs[ua][vb]) +
                   (1.0f - wyc) * (wxc * hs[ub][va] + (1.0f - wxc) * hs[ub][vb]);

        // ll1/hi1 bilinear (global, L1-resident)
        int ti = i >> 1;
        int ra, rb;
        float wra;
        if ((i & 1) == 0) { ra = max(ti - 1, 0); rb = ti; wra = 0.25f; }
        else              { ra = ti; rb = min(ti + 1, 127); wra = 0.75f; }
        float wrb = 1.0f - wra;

        int oa = ra * 128, ob = rb * 128;
        float h1 = wra * (wca * __ldg(H1 + oa + ca) + wcb * __ldg(H1 + oa + cb)) +
                   wrb * (wca * __ldg(H1 + ob + ca) + wcb * __ldg(H1 + ob + cb));
        float lo = wra * (wca * __ldg(L1 + oa + ca) + wcb * __ldg(L1 + oa + cb)) +
                   wrb * (wca * __ldg(L1 + ob + ca) + wcb * __ldg(L1 + ob + cb));

        size_t o = (size_t)ch * IMG + (size_t)i * HW + j;
        out_low[o] = lo;
        out_high[o] = 0.5f * (h0 + h1);
    }
}

extern "C" void kernel_launch(void* const* d_in, const int* in_sizes, int n_in,
                              void* d_out, int out_size) {
    const float* x = (const float*)d_in[0];
    float* out = (float*)d_out;
    int nc = in_sizes[0] / IMG;  // 512 for (8,64,256,256)
    if (nc > NC_MAX) nc = NC_MAX;

    dim3 b1(32, 8);
    dim3 g1(128 / 32, 128 / 8, nc);
    k_level1<<<g1, b1>>>(x);

    dim3 b2(32, 8);
    dim3 g2(HW / 32, HW / 32, nc);
    k_out<<<g2, b2>>>(x, out, nc);
}

// round 4
// speedup vs baseline: 1.4916x; 1.4916x over previous
#include <cuda_runtime.h>

// HaarWavelet2D level=2, x:(8,64,256,256) fp32 -> (low,high) each (8,64,256,256)
// Single fused kernel. Per 32x32 output tile:
//   xs  (38x38, halo 3)  : clamped x tile
//   LLs (37x37)          : level-0 LL (ll0) at global rows/cols i0-3..i0+33
//   hs  (33x33)          : hi0 = |lh0|+|hl0|+|hh0| at rows i0-1..i0+31
//   l1s/h1s (18x18)      : ll1 / hi1 at rows i0/2-1..i0/2+16
// Epilogue: one thread = one 2x2 output quad (bilinear resizes, all smem).
//
// Resize identities (jax.image.resize 'linear', half-pixel, clamped):
//   255->256: out[i] = w*X[max(i-1,0)] + (1-w)*X[min(i,254)], w=(i+0.5)/256
//   128->256: even i=2t: 0.25*X[max(t-1,0)] + 0.75*X[t]
//             odd  i=2t+1: 0.75*X[t] + 0.25*X[min(t+1,127)]

#define HW 256
#define IMG (HW*HW)
#define INV256 (1.0f/256.0f)

__device__ __forceinline__ int clampi(int v, int lo, int hi) {
    return v < lo ? lo : (v > hi ? hi : v);
}

__global__ void __launch_bounds__(256) k_fused(const float* __restrict__ x,
                                               float* __restrict__ out, int nc) {
    __shared__ float xs[38][40];
    __shared__ float LLs[37][40];
    __shared__ float hs[33][36];
    __shared__ float l1s[18][20];
    __shared__ float h1s[18][20];

    const int ch = blockIdx.z;
    const int i0 = blockIdx.y * 32;
    const int j0 = blockIdx.x * 32;
    const int tid = threadIdx.x;
    const float* xc = x + (size_t)ch * IMG;

    // ---- stage 1: x tile with halo 3 (clamped) ----
    // xs[u][v] = x[clamp(i0-3+u)][clamp(j0-3+v)]
#pragma unroll
    for (int e = tid; e < 38 * 38; e += 256) {
        int u = e / 38, v = e - u * 38;
        int r = clampi(i0 - 3 + u, 0, 255);
        int c = clampi(j0 - 3 + v, 0, 255);
        xs[u][v] = __ldg(xc + r * HW + c);
    }
    __syncthreads();

    // ---- stage 2a: LL (ll0) tile. LLs[u][v] ~ ll0(i0-3+u, j0-3+v) ----
    // valid wherever the global index is in [0,254]; out-of-range entries
    // are never read by stage 3.
#pragma unroll
    for (int e = tid; e < 37 * 37; e += 256) {
        int u = e / 37, v = e - u * 37;
        LLs[u][v] = 0.25f * (xs[u][v] + xs[u][v + 1] + xs[u + 1][v] + xs[u + 1][v + 1]);
    }
    // ---- stage 2b: hi0 tile. hs[u][v] ~ hi0(i0-1+u, j0-1+v) ----
#pragma unroll
    for (int e = tid; e < 33 * 33; e += 256) {
        int u = e / 33, v = e - u * 33;
        float a = xs[u + 2][v + 2], b = xs[u + 2][v + 3];
        float c = xs[u + 3][v + 2], d = xs[u + 3][v + 3];
        float lh = 0.25f * (a + b - c - d);
        float hl = 0.25f * (a - b + c - d);
        float hh = 0.25f * (a - b - c + d);
        hs[u][v] = fabsf(lh) + fabsf(hl) + fabsf(hh);
    }
    __syncthreads();

    // ---- stage 3: ll1 / hi1 tile from LLs ----
    // l1s[u][v] = ll1(A0+u, B0+v), A0 = i0/2-1, B0 = j0/2-1 (clamped compute,
    // out-of-range entries never read).
    const int A0 = (i0 >> 1) - 1;
    const int B0 = (j0 >> 1) - 1;
    const int K0 = i0 - 3;   // LLs row base (global)
    const int L0 = j0 - 3;   // LLs col base (global)
#pragma unroll
    for (int e = tid; e < 18 * 18; e += 256) {
        int u = e / 18, v = e - u * 18;
        int a = clampi(A0 + u, 0, 127);
        int b = clampi(B0 + v, 0, 127);
        int rm = clampi(2 * a - 1, 0, 254) - K0;
        int r0 = 2 * a - K0;
        int rp = clampi(2 * a + 1, 0, 254) - K0;
        int cm = clampi(2 * b - 1, 0, 254) - L0;
        int c0 = 2 * b - L0;
        int cp = clampi(2 * b + 1, 0, 254) - L0;
        float wy0 = (2 * a + 0.5f) * INV256;
        float wy1 = (2 * a + 1.5f) * INV256;
        float wx0 = (2 * b + 0.5f) * INV256;
        float wx1 = (2 * b + 1.5f) * INV256;

        // column interpolation on 3 LL rows (A: col 2b, B: col 2b+1)
        float Am = wx0 * LLs[rm][cm] + (1.0f - wx0) * LLs[rm][c0];
        float A0r = wx0 * LLs[r0][cm] + (1.0f - wx0) * LLs[r0][c0];
        float Ap = wx0 * LLs[rp][cm] + (1.0f - wx0) * LLs[rp][c0];
        float Bm = wx1 * LLs[rm][c0] + (1.0f - wx1) * LLs[rm][cp];
        float B0r = wx1 * LLs[r0][c0] + (1.0f - wx1) * LLs[r0][cp];
        float Bp = wx1 * LLs[rp][c0] + (1.0f - wx1) * LLs[rp][cp];

        float L00 = wy0 * Am + (1.0f - wy0) * A0r;   // low0(2a,   2b)
        float L01 = wy0 * Bm + (1.0f - wy0) * B0r;   // low0(2a,   2b+1)
        float L10 = wy1 * A0r + (1.0f - wy1) * Ap;   // low0(2a+1, 2b)
        float L11 = wy1 * B0r + (1.0f - wy1) * Bp;   // low0(2a+1, 2b+1)

        float ll = 0.25f * (L00 + L01 + L10 + L11);
        float lh = 0.25f * (L00 + L01 - L10 - L11);
        float hl = 0.25f * (L00 - L01 + L10 - L11);
        float hh = 0.25f * (L00 - L01 - L10 + L11);
        l1s[u][v] = ll;
        h1s[u][v] = fabsf(lh) + fabsf(hl) + fabsf(hh);
    }
    __syncthreads();

    // ---- stage 4: epilogue. One 2x2 output quad per thread. ----
    const int qx = tid & 15;
    const int qy = tid >> 4;
    const int p = (i0 >> 1) + qy;   // quad row  (output rows 2p, 2p+1)
    const int q = (j0 >> 1) + qx;   // quad col  (output cols 2q, 2q+1)

    // --- hi0 resize (255->256), hs base (i0-1, j0-1) ---
    const int hrm = max(2 * p - 1, 0) - (i0 - 1);
    const int hr0 = 2 * p - (i0 - 1);
    const int hrp = min(2 * p + 1, 254) - (i0 - 1);
    const int hcm = max(2 * q - 1, 0) - (j0 - 1);
    const int hc0 = 2 * q - (j0 - 1);
    const int hcp = min(2 * q + 1, 254) - (j0 - 1);
    const float wyi0 = (2 * p + 0.5f) * INV256;   // weight on row tap (i-1) for i=2p
    const float wyi1 = (2 * p + 1.5f) * INV256;   // for i=2p+1
    const float wxj0 = (2 * q + 0.5f) * INV256;
    const float wxj1 = (2 * q + 1.5f) * INV256;

    float hAm = wxj0 * hs[hrm][hcm] + (1.0f - wxj0) * hs[hrm][hc0];
    float hA0 = wxj0 * hs[hr0][hcm] + (1.0f - wxj0) * hs[hr0][hc0];
    float hAp = wxj0 * hs[hrp][hcm] + (1.0f - wxj0) * hs[hrp][hc0];
    float hBm = wxj1 * hs[hrm][hc0] + (1.0f - wxj1) * hs[hrm][hcp];
    float hB0 = wxj1 * hs[hr0][hc0] + (1.0f - wxj1) * hs[hr0][hcp];
    float hBp = wxj1 * hs[hrp][hc0] + (1.0f - wxj1) * hs[hrp][hcp];

    float h0_00 = wyi0 * hAm + (1.0f - wyi0) * hA0;  // (2p,   2q)
    float h0_01 = wyi0 * hBm + (1.0f - wyi0) * hB0;  // (2p,   2q+1)
    float h0_10 = wyi1 * hA0 + (1.0f - wyi1) * hAp;  // (2p+1, 2q)
    float h0_11 = wyi1 * hB0 + (1.0f - wyi1) * hBp;  // (2p+1, 2q+1)

    // --- ll1/hi1 resize (128->256), base (A0, B0) ---
    const int rm1 = max(p - 1, 0) - A0;
    const int r01 = p - A0;                 // = qy + 1
    const int rp1 = min(p + 1, 127) - A0;
    const int cm1 = max(q - 1, 0) - B0;
    const int c01 = q - B0;                 // = qx + 1
    const int cp1 = min(q + 1, 127) - B0;

    // ll1
    float lAm = 0.25f * l1s[rm1][cm1] + 0.75f * l1s[rm1][c01];
    float lA0 = 0.25f * l1s[r01][cm1] + 0.75f * l1s[r01][c01];
    float lAp = 0.25f * l1s[rp1][cm1] + 0.75f * l1s[rp1][c01];
    float lBm = 0.75f * l1s[rm1][c01] + 0.25f * l1s[rm1][cp1];
    float lB0 = 0.75f * l1s[r01][c01] + 0.25f * l1s[r01][cp1];
    float lBp = 0.75f * l1s[rp1][c01] + 0.25f * l1s[rp1][cp1];

    float lo00 = 0.25f * lAm + 0.75f * lA0;
    float lo01 = 0.25f * lBm + 0.75f * lB0;
    float lo10 = 0.75f * lA0 + 0.25f * lAp;
    float lo11 = 0.75f * lB0 + 0.25f * lBp;

    // hi1
    float gAm = 0.25f * h1s[rm1][cm1] + 0.75f * h1s[rm1][c01];
    float gA0 = 0.25f * h1s[r01][cm1] + 0.75f * h1s[r01][c01];
    float gAp = 0.25f * h1s[rp1][cm1] + 0.75f * h1s[rp1][c01];
    float gBm = 0.75f * h1s[rm1][c01] + 0.25f * h1s[rm1][cp1];
    float gB0 = 0.75f * h1s[r01][c01] + 0.25f * h1s[r01][cp1];
    float gBp = 0.75f * h1s[rp1][c01] + 0.25f * h1s[rp1][cp1];

    float h1_00 = 0.25f * gAm + 0.75f * gA0;
    float h1_01 = 0.25f * gBm + 0.75f * gB0;
    float h1_10 = 0.75f * gA0 + 0.25f * gAp;
    float h1_11 = 0.75f * gB0 + 0.25f * gBp;

    // --- stores (float2, rows 2p and 2p+1, cols 2q..2q+1) ---
    const size_t nimg = (size_t)nc * IMG;
    float* out_low = out;
    float* out_high = out + nimg;
    const size_t base0 = (size_t)ch * IMG + (size_t)(2 * p) * HW + 2 * q;
    const size_t base1 = base0 + HW;

    *reinterpret_cast<float2*>(out_low + base0) = make_float2(lo00, lo01);
    *reinterpret_cast<float2*>(out_low + base1) = make_float2(lo10, lo11);
    *reinterpret_cast<float2*>(out_high + base0) =
        make_float2(0.5f * (h0_00 + h1_00), 0.5f * (h0_01 + h1_01));
    *reinterpret_cast<float2*>(out_high + base1) =
        make_float2(0.5f * (h0_10 + h1_10), 0.5f * (h0_11 + h1_11));
}

extern "C" void kernel_launch(void* const* d_in, const int* in_sizes, int n_in,
                              void* d_out, int out_size) {
    const float* x = (const float*)d_in[0];
    float* out = (float*)d_out;
    int nc = in_sizes[0] / IMG;  // 512 for (8,64,256,256)

    dim3 blk(256);
    dim3 grd(HW / 32, HW / 32, nc);
    k_fused<<<grd, blk>>>(x, out, nc);
}